// round 17
// baseline (speedup 1.0000x reference)
#include <cuda_runtime.h>
#include <cuda_fp16.h>
#include <cstdint>

#define BB   8
#define LLEN 4096
#define CEMB 192
#define DIN  384
#define XD   20
#define DTR  12
#define NC   128
#define LC   32
#define MROWS (BB*LLEN)

// ---------------- scratch ----------------
__device__ float g_xh  [MROWS*CEMB];      // residual (fp32)
__device__ __half g_xzh[MROWS*2*DIN];     // in_proj output
__device__ __half g_xah[MROWS*DIN];       // conv+silu output
__device__ __half g_xdh[MROWS*64];        // x_dbl (dt_lr 0..11 | B 12..15 | C 16..19)
__device__ __half g_dth[MROWS*DIN];       // dt (post-softplus)
__device__ float g_hpart[BB*DIN*NC*4];
__device__ float g_sumdt[BB*DIN*NC];
__device__ float g_Hinit[BB*DIN*NC*4];
__device__ float g_A[2*DIN*4];
__device__ int   g_slow[2];
__device__ float g_Uf[4*DIN];
__device__ __half g_ah[MROWS*DIN];        // xh -> y (GEMM A / final y)
__device__ __half g_bh[MROWS*CEMB];       // h2
__device__ __half g_wh[2*768*CEMB + CEMB*DIN];  // inproj0 | inproj1 | outproj0
__device__ __half g_wxp[2*64*DIN];        // padded x_proj weights [64,384]
__device__ __half g_wdt[2*DIN*64];        // padded dt weights [384,64]

__device__ __forceinline__ uint32_t smem_u32(const void* p) {
    uint32_t a;
    asm("{ .reg .u64 t; cvta.to.shared.u64 t, %1; cvt.u32.u64 %0, t; }" : "=r"(a) : "l"(p));
    return a;
}
__device__ __forceinline__ float4 ld4h(const __half* p) {
    uint2 u = *(const uint2*)p;
    __half2 h0 = *(__half2*)&u.x, h1 = *(__half2*)&u.y;
    float2 f0 = __half22float2(h0), f1 = __half22float2(h1);
    return make_float4(f0.x, f0.y, f1.x, f1.y);
}
__device__ __forceinline__ void st4h(__half* p, float4 v) {
    uint32_t p0, p1;
    asm("cvt.rn.f16x2.f32 %0, %1, %2;" : "=r"(p0) : "f"(v.y), "f"(v.x));
    asm("cvt.rn.f16x2.f32 %0, %1, %2;" : "=r"(p1) : "f"(v.w), "f"(v.z));
    *(uint2*)p = make_uint2(p0, p1);
}

#define LDSM_X4(r0, r1, r2, r3, addr) \
    asm volatile("ldmatrix.sync.aligned.m8n8.x4.shared.b16 {%0,%1,%2,%3}, [%4];" \
        : "=r"(r0), "=r"(r1), "=r"(r2), "=r"(r3) : "r"(addr))
#define LDSM_X2(r0, r1, addr) \
    asm volatile("ldmatrix.sync.aligned.m8n8.x2.shared.b16 {%0,%1}, [%2];" \
        : "=r"(r0), "=r"(r1) : "r"(addr))
#define MMA_F16(c, a, b) \
    asm volatile("mma.sync.aligned.m16n8k16.row.col.f32.f16.f16.f32 " \
        "{%0,%1,%2,%3}, {%4,%5,%6,%7}, {%8,%9}, {%0,%1,%2,%3};" \
        : "+f"((c)[0]), "+f"((c)[1]), "+f"((c)[2]), "+f"((c)[3]) \
        : "r"((a)[0]), "r"((a)[1]), "r"((a)[2]), "r"((a)[3]), "r"((b)[0]), "r"((b)[1]))

// ======================= fp16 HMMA GEMM =======================
// mode 1: fp16 out; mode 2: fp16 out with +bias[col] then softplus
__global__ void __launch_bounds__(256, 2)
gemm_mma(const __half* __restrict__ A, const __half* __restrict__ W,
         __half* __restrict__ Ch, const float* __restrict__ bias,
         int M, int N, int K, int mode)
{
    __shared__ __align__(1024) char sm[24576];
    char* AH = sm;
    char* WH = sm + 16384;

    const int tid = threadIdx.x, wid = tid >> 5, lane = tid & 31;
    const int wm = wid & 3, wn = wid >> 2;
    const int bm = blockIdx.y * 128, bn = blockIdx.x * 64;
    const uint32_t sAH = smem_u32(AH), sWH = smem_u32(WH);

    float acc[2][4][4];
    #pragma unroll
    for (int i = 0; i < 2; i++)
        #pragma unroll
        for (int j = 0; j < 4; j++)
            #pragma unroll
            for (int q = 0; q < 4; q++) acc[i][j][q] = 0.f;

    uint4 ra[4], rw[2];
    const int nkt = K >> 6;

    #pragma unroll
    for (int i = 0; i < 4; i++) {
        int idx = tid + i * 256, r = idx >> 3, q = idx & 7;
        ra[i] = *(const uint4*)(A + (size_t)(bm + r) * K + q * 8);
    }
    #pragma unroll
    for (int i = 0; i < 2; i++) {
        int idx = tid + i * 256, r = idx >> 3, q = idx & 7;
        rw[i] = *(const uint4*)(W + (size_t)(bn + r) * K + q * 8);
    }

    for (int kt = 0; kt < nkt; kt++) {
        #pragma unroll
        for (int i = 0; i < 4; i++) {
            int idx = tid + i * 256, r = idx >> 3, q = idx & 7;
            *(uint4*)(AH + r * 128 + ((q ^ (r & 7)) << 4)) = ra[i];
        }
        #pragma unroll
        for (int i = 0; i < 2; i++) {
            int idx = tid + i * 256, r = idx >> 3, q = idx & 7;
            *(uint4*)(WH + r * 128 + ((q ^ (r & 7)) << 4)) = rw[i];
        }
        __syncthreads();

        if (kt + 1 < nkt) {
            int k0 = (kt + 1) * 64;
            #pragma unroll
            for (int i = 0; i < 4; i++) {
                int idx = tid + i * 256, r = idx >> 3, q = idx & 7;
                ra[i] = *(const uint4*)(A + (size_t)(bm + r) * K + k0 + q * 8);
            }
            #pragma unroll
            for (int i = 0; i < 2; i++) {
                int idx = tid + i * 256, r = idx >> 3, q = idx & 7;
                rw[i] = *(const uint4*)(W + (size_t)(bn + r) * K + k0 + q * 8);
            }
        }

        #pragma unroll
        for (int ks = 0; ks < 4; ks++) {
            uint32_t ah[2][4], bh[4][2];
            #pragma unroll
            for (int mt = 0; mt < 2; mt++) {
                int r = wm * 32 + mt * 16 + (lane & 15);
                int c16 = ks * 2 + (lane >> 4);
                LDSM_X4(ah[mt][0], ah[mt][1], ah[mt][2], ah[mt][3],
                        sAH + r * 128 + ((c16 ^ (r & 7)) << 4));
            }
            #pragma unroll
            for (int nt = 0; nt < 4; nt++) {
                int rn = wn * 32 + nt * 8 + (lane & 7);
                int c16 = ks * 2 + ((lane >> 3) & 1);
                LDSM_X2(bh[nt][0], bh[nt][1],
                        sWH + rn * 128 + ((c16 ^ (rn & 7)) << 4));
            }
            #pragma unroll
            for (int mt = 0; mt < 2; mt++)
                #pragma unroll
                for (int nt = 0; nt < 4; nt++)
                    MMA_F16(acc[mt][nt], ah[mt], bh[nt]);
        }
        __syncthreads();
    }

    #pragma unroll
    for (int mt = 0; mt < 2; mt++) {
        int row = bm + wm * 32 + mt * 16 + (lane >> 2);
        #pragma unroll
        for (int nt = 0; nt < 4; nt++) {
            int col = bn + wn * 32 + nt * 8 + (lane & 3) * 2;
            #pragma unroll
            for (int hh = 0; hh < 2; hh++) {
                float a0 = acc[mt][nt][hh*2+0], a1 = acc[mt][nt][hh*2+1];
                if (mode == 2) {
                    a0 += bias[col];
                    a1 += bias[col + 1];
                    a0 = (a0 > 20.f) ? a0 : __logf(1.f + __expf(a0));
                    a1 = (a1 > 20.f) ? a1 : __logf(1.f + __expf(a1));
                }
                uint32_t hp;
                asm("cvt.rn.f16x2.f32 %0, %1, %2;" : "=r"(hp) : "f"(a1), "f"(a0));
                *(uint32_t*)(Ch + (size_t)(row + hh*8) * N + col) = hp;
            }
        }
    }
}

// ---------------- weight converts ----------------
__global__ void wcvt_k(const float* __restrict__ src, int n4, int dst4) {
    int idx = blockIdx.x * blockDim.x + threadIdx.x;
    if (idx >= n4) return;
    float4 v = ((const float4*)src)[idx];
    uint32_t p0, p1;
    asm("cvt.rn.f16x2.f32 %0, %1, %2;" : "=r"(p0) : "f"(v.y), "f"(v.x));
    asm("cvt.rn.f16x2.f32 %0, %1, %2;" : "=r"(p1) : "f"(v.w), "f"(v.z));
    ((uint2*)g_wh)[dst4 + idx] = make_uint2(p0, p1);
}
__global__ void wcvtx_k(const float* __restrict__ src, int mix) {
    int idx = blockIdx.x * blockDim.x + threadIdx.x;
    if (idx >= 64 * DIN / 4) return;
    int n = (idx * 4) / DIN;
    uint2 o = make_uint2(0, 0);
    if (n < XD) {
        float4 v = ((const float4*)src)[idx];
        asm("cvt.rn.f16x2.f32 %0, %1, %2;" : "=r"(o.x) : "f"(v.y), "f"(v.x));
        asm("cvt.rn.f16x2.f32 %0, %1, %2;" : "=r"(o.y) : "f"(v.w), "f"(v.z));
    }
    ((uint2*)(g_wxp + (size_t)mix * 64 * DIN))[idx] = o;
}
__global__ void wcvtd_k(const float* __restrict__ src, int mix) {   // [384,12] -> [384,64] padded
    int idx = blockIdx.x * blockDim.x + threadIdx.x;
    if (idx >= DIN * 64) return;
    int d = idx >> 6, k = idx & 63;
    float v = (k < DTR) ? src[d * DTR + k] : 0.f;
    g_wdt[(size_t)mix * DIN * 64 + idx] = __float2half_rn(v);
}

// ---------------- transpose ----------------
__global__ void transpose_k(const float* __restrict__ x) {
    __shared__ float t[32][33];
    int b = blockIdx.z;
    int l0 = blockIdx.x * 32, c0 = blockIdx.y * 32;
    int tx = threadIdx.x, ty = threadIdx.y;
    #pragma unroll
    for (int j = ty; j < 32; j += 8)
        t[j][tx] = x[((b*CEMB) + (c0 + j)) * LLEN + l0 + tx];
    __syncthreads();
    #pragma unroll
    for (int j = ty; j < 32; j += 8) {
        float v = t[tx][j];
        size_t idx = ((size_t)(b*LLEN) + (l0 + j)) * CEMB + c0 + tx;
        g_xh[idx] = v;
        g_ah[idx] = __float2half_rn(v);
    }
}

// ---------------- A structure prep ----------------
__global__ void prepA_k(const float* __restrict__ A_log) {
    int mix = blockIdx.x;
    int d = threadIdx.x;
    if (d == 0) g_slow[mix] = 0;
    __syncthreads();
    const float* al = A_log + mix * DIN * 4;
    float a[4];
    #pragma unroll
    for (int s = 0; s < 4; s++) {
        a[s] = -expf(al[d*4 + s]);
        g_A[(mix*DIN + d)*4 + s] = a[s];
    }
    bool ok = true;
    #pragma unroll
    for (int s = 0; s < 4; s++) {
        float want = (float)(s + 1) * a[0];
        if (fabsf(a[s] - want) > 1e-5f * fabsf(a[s]) + 1e-7f) ok = false;
    }
    if (!ok) atomicExch(&g_slow[mix], 1);
}

// ---------------- Uf = U_w @ Wout2 ----------------
__global__ void uf_k(const float* __restrict__ U, const float* __restrict__ Wout2) {
    __shared__ float Ush[4*CEMB];
    int k = threadIdx.x;
    for (int i = k; i < 4*CEMB; i += DIN) Ush[i] = U[i];
    __syncthreads();
    float acc0 = 0.f, acc1 = 0.f, acc2 = 0.f, acc3 = 0.f;
    for (int c = 0; c < CEMB; c++) {
        float w = Wout2[(size_t)c * DIN + k];
        acc0 = fmaf(Ush[0*CEMB + c], w, acc0);
        acc1 = fmaf(Ush[1*CEMB + c], w, acc1);
        acc2 = fmaf(Ush[2*CEMB + c], w, acc2);
        acc3 = fmaf(Ush[3*CEMB + c], w, acc3);
    }
    g_Uf[0*DIN + k] = acc0;
    g_Uf[1*DIN + k] = acc1;
    g_Uf[2*DIN + k] = acc2;
    g_Uf[3*DIN + k] = acc3;
}

// ---------------- depthwise causal conv + silu ----------------
__global__ void __launch_bounds__(256)
conv_k(const float* __restrict__ w, const float* __restrict__ bias) {
    int idx = blockIdx.x * blockDim.x + threadIdx.x;
    if (idx >= (MROWS/8) * (DIN/4)) return;
    int d4 = idx % (DIN/4);
    int m8 = idx / (DIN/4);
    int d  = d4 * 4;
    int bl = m8 * 8;
    int l  = bl % LLEN;

    float4 wv0 = *(const float4*)(w + (d+0)*4);
    float4 wv1 = *(const float4*)(w + (d+1)*4);
    float4 wv2 = *(const float4*)(w + (d+2)*4);
    float4 wv3 = *(const float4*)(w + (d+3)*4);
    float4 bv  = *(const float4*)(bias + d);

    const __half* p = g_xzh + (size_t)bl * (2*DIN) + d;
    __half* po = g_xah + (size_t)bl * DIN + d;
    float4 x1 = make_float4(0,0,0,0), x2 = x1, x3 = x1;
    if (l) {
        x3 = ld4h(p - 3*2*DIN);
        x2 = ld4h(p - 2*2*DIN);
        x1 = ld4h(p - 2*DIN);
    }
    #pragma unroll
    for (int j = 0; j < 8; j++) {
        float4 x0 = ld4h(p + j*2*DIN);
        float4 acc = bv;
        acc.x = fmaf(wv0.x, x3.x, acc.x); acc.y = fmaf(wv1.x, x3.y, acc.y);
        acc.z = fmaf(wv2.x, x3.z, acc.z); acc.w = fmaf(wv3.x, x3.w, acc.w);
        acc.x = fmaf(wv0.y, x2.x, acc.x); acc.y = fmaf(wv1.y, x2.y, acc.y);
        acc.z = fmaf(wv2.y, x2.z, acc.z); acc.w = fmaf(wv3.y, x2.w, acc.w);
        acc.x = fmaf(wv0.z, x1.x, acc.x); acc.y = fmaf(wv1.z, x1.y, acc.y);
        acc.z = fmaf(wv2.z, x1.z, acc.z); acc.w = fmaf(wv3.z, x1.w, acc.w);
        acc.x = fmaf(wv0.w, x0.x, acc.x); acc.y = fmaf(wv1.w, x0.y, acc.y);
        acc.z = fmaf(wv2.w, x0.z, acc.z); acc.w = fmaf(wv3.w, x0.w, acc.w);
        float4 s;
        s.x = __fdividef(acc.x, 1.f + __expf(-acc.x));
        s.y = __fdividef(acc.y, 1.f + __expf(-acc.y));
        s.z = __fdividef(acc.z, 1.f + __expf(-acc.z));
        s.w = __fdividef(acc.w, 1.f + __expf(-acc.w));
        st4h(po + j*DIN, s);
        x3 = x2; x2 = x1; x1 = x0;
    }
}

// ---------------- scan pass 1 (dt precomputed) ----------------
__global__ void scan1_k(int mix) {
    __shared__ float Bsm[LC][4];
    int chunk = blockIdx.x, b = blockIdx.y, d = threadIdx.x;
    int l0 = chunk * LC;
    if (threadIdx.x < LC*4) {
        int l = threadIdx.x >> 2, s = threadIdx.x & 3;
        Bsm[l][s] = __half2float(g_xdh[((size_t)(b*LLEN + l0 + l))*64 + DTR + s]);
    }
    __syncthreads();
    int slow = g_slow[mix];
    const float* Ab = g_A + (mix*DIN + d)*4;
    float Av0 = Ab[0], Av1 = Ab[1], Av2 = Ab[2], Av3 = Ab[3];
    float h0 = 0.f, h1 = 0.f, h2 = 0.f, h3 = 0.f, sd = 0.f;
    size_t base = (size_t)(b*LLEN + l0)*DIN + d;
    const __half* pa = g_xah + base;
    const __half* pd = g_dth + base;
    #pragma unroll 4
    for (int l = 0; l < LC; l++) {
        float xav = __half2float(pa[l*DIN]);
        float dtv = __half2float(pd[l*DIN]);
        float dbu = dtv * xav;
        sd += dtv;
        float b0 = Bsm[l][0], b1 = Bsm[l][1], b2 = Bsm[l][2], b3 = Bsm[l][3];
        if (!slow) {
            float e = __expf(Av0 * dtv);
            float q = e;
            h0 = fmaf(q, h0, dbu*b0); q *= e;
            h1 = fmaf(q, h1, dbu*b1); q *= e;
            h2 = fmaf(q, h2, dbu*b2); q *= e;
            h3 = fmaf(q, h3, dbu*b3);
        } else {
            h0 = fmaf(__expf(dtv*Av0), h0, dbu*b0);
            h1 = fmaf(__expf(dtv*Av1), h1, dbu*b1);
            h2 = fmaf(__expf(dtv*Av2), h2, dbu*b2);
            h3 = fmaf(__expf(dtv*Av3), h3, dbu*b3);
        }
    }
    int o = ((b*DIN) + d)*NC + chunk;
    ((float4*)g_hpart)[o] = make_float4(h0, h1, h2, h3);
    g_sumdt[o] = sd;
}

// ---------------- scan pass 2 ----------------
__global__ void scan2_k(int mix) {
    int t = blockIdx.x * blockDim.x + threadIdx.x;
    if (t >= BB*DIN) return;
    int d = t % DIN;
    const float* Ab = g_A + (mix*DIN + d)*4;
    float Av0 = Ab[0], Av1 = Ab[1], Av2 = Ab[2], Av3 = Ab[3];
    float H0 = 0.f, H1 = 0.f, H2 = 0.f, H3 = 0.f;
    for (int c = 0; c < NC; c++) {
        int o = t*NC + c;
        ((float4*)g_Hinit)[o] = make_float4(H0, H1, H2, H3);
        float4 hp = ((const float4*)g_hpart)[o];
        float sd = g_sumdt[o];
        H0 = fmaf(__expf(Av0*sd), H0, hp.x);
        H1 = fmaf(__expf(Av1*sd), H1, hp.y);
        H2 = fmaf(__expf(Av2*sd), H2, hp.z);
        H3 = fmaf(__expf(Av3*sd), H3, hp.w);
    }
}

// ---------------- scan pass 3 (dt precomputed; writes half y) ----------------
__global__ void scan3_k(const float* __restrict__ Dw, int mix) {
    __shared__ float Bsm[LC][4];
    __shared__ float Csm[LC][4];
    int chunk = blockIdx.x, b = blockIdx.y, d = threadIdx.x;
    int l0 = chunk * LC;
    if (threadIdx.x < LC*8) {
        int l = threadIdx.x >> 3, s = threadIdx.x & 7;
        float v = __half2float(g_xdh[((size_t)(b*LLEN + l0 + l))*64 + DTR + s]);
        if (s < 4) Bsm[l][s] = v; else Csm[l][s-4] = v;
    }
    __syncthreads();
    int slow = g_slow[mix];
    const float* Ab = g_A + (mix*DIN + d)*4;
    float Av0 = Ab[0], Av1 = Ab[1], Av2 = Ab[2], Av3 = Ab[3];
    float Dd = Dw[d];
    int o = ((b*DIN) + d)*NC + chunk;
    float4 Hi = ((const float4*)g_Hinit)[o];
    float h0 = Hi.x, h1 = Hi.y, h2 = Hi.z, h3 = Hi.w;
    size_t base = (size_t)(b*LLEN + l0)*DIN + d;
    const __half* pa = g_xah + base;
    const __half* pd = g_dth + base;
    const __half* pz = g_xzh + (size_t)(b*LLEN + l0)*(2*DIN) + DIN + d;
    #pragma unroll 4
    for (int l = 0; l < LC; l++) {
        float xav = __half2float(pa[l*DIN]);
        float dtv = __half2float(pd[l*DIN]);
        float dbu = dtv * xav;
        float b0 = Bsm[l][0], b1 = Bsm[l][1], b2 = Bsm[l][2], b3 = Bsm[l][3];
        if (!slow) {
            float e = __expf(Av0 * dtv);
            float q = e;
            h0 = fmaf(q, h0, dbu*b0); q *= e;
            h1 = fmaf(q, h1, dbu*b1); q *= e;
            h2 = fmaf(q, h2, dbu*b2); q *= e;
            h3 = fmaf(q, h3, dbu*b3);
        } else {
            h0 = fmaf(__expf(dtv*Av0), h0, dbu*b0);
            h1 = fmaf(__expf(dtv*Av1), h1, dbu*b1);
            h2 = fmaf(__expf(dtv*Av2), h2, dbu*b2);
            h3 = fmaf(__expf(dtv*Av3), h3, dbu*b3);
        }
        float y = h0*Csm[l][0] + h1*Csm[l][1] + h2*Csm[l][2] + h3*Csm[l][3];
        y = fmaf(xav, Dd, y);
        float zv = __half2float(pz[l*2*DIN]);
        float zs = __fdividef(zv, 1.f + __expf(-zv));
        g_ah[base + l*DIN] = __float2half_rn(y * zs);
    }
}

// ---------------- final: u = y2 @ Uf^T; out = LN(xh + u @ V^T) ----------------
__global__ void final_k(const float* __restrict__ V,
                        const float* __restrict__ lng, const float* __restrict__ lnb,
                        float* __restrict__ out)
{
    __shared__ __align__(16) float Ufs[4*DIN];
    __shared__ float Vsh[CEMB*4];
    __shared__ float u[32][4];
    __shared__ float vs[32][193];
    __shared__ float mu[32], rsd[32];
    int b = blockIdx.y;
    int l0 = blockIdx.x * 32;
    int tid = threadIdx.x;
    for (int i = tid; i < 4*DIN; i += 256) Ufs[i] = g_Uf[i];
    for (int i = tid; i < 4*CEMB; i += 256) Vsh[i] = V[i];
    __syncthreads();
    if (tid < 128) {
        int p = tid >> 2, r = tid & 3;
        const __half* yr = g_ah + ((size_t)(b*LLEN) + l0 + p)*DIN;
        const float4* uf = (const float4*)(Ufs + r*DIN);
        float a = 0.f;
        #pragma unroll 8
        for (int c = 0; c < DIN/4; c++) {
            float4 yv = ld4h(yr + c*4);
            float4 wv = uf[c];
            a = fmaf(yv.x, wv.x, fmaf(yv.y, wv.y, fmaf(yv.z, wv.z, fmaf(yv.w, wv.w, a))));
        }
        u[p][r] = a;
    }
    __syncthreads();
    for (int i = tid; i < 32*CEMB; i += 256) {
        int p = i / CEMB, c = i % CEMB;
        float v = g_xh[((size_t)(b*LLEN) + l0 + p)*CEMB + c];
        v = fmaf(Vsh[c*4+0], u[p][0], v);
        v = fmaf(Vsh[c*4+1], u[p][1], v);
        v = fmaf(Vsh[c*4+2], u[p][2], v);
        v = fmaf(Vsh[c*4+3], u[p][3], v);
        vs[p][c] = v;
    }
    __syncthreads();
    int warp = tid >> 5, lane = tid & 31;
    #pragma unroll
    for (int pp = 0; pp < 4; pp++) {
        int p = warp*4 + pp;
        float s = 0.f, ss = 0.f;
        for (int c = lane; c < CEMB; c += 32) {
            float v = vs[p][c];
            s += v; ss = fmaf(v, v, ss);
        }
        #pragma unroll
        for (int off = 16; off > 0; off >>= 1) {
            s  += __shfl_xor_sync(0xffffffffu, s, off);
            ss += __shfl_xor_sync(0xffffffffu, ss, off);
        }
        if (lane == 0) {
            float m = s * (1.f/CEMB);
            mu[p] = m;
            rsd[p] = rsqrtf(ss * (1.f/CEMB) - m*m + 1e-5f);
        }
    }
    __syncthreads();
    for (int c = warp; c < CEMB; c += 8) {
        int p = lane;
        float v = (vs[p][c] - mu[p]) * rsd[p] * lng[c] + lnb[c];
        out[((size_t)(b*CEMB) + c)*LLEN + l0 + lane] = v;
    }
}

// ---------------- launch ----------------
extern "C" void kernel_launch(void* const* d_in, const int* in_sizes, int n_in,
                              void* d_out, int out_size)
{
    const float* x         = (const float*)d_in[0];
    const float* in_proj_w = (const float*)d_in[1];
    const float* conv_w    = (const float*)d_in[2];
    const float* conv_b    = (const float*)d_in[3];
    const float* x_proj_w  = (const float*)d_in[4];
    const float* dt_proj_w = (const float*)d_in[5];
    const float* dt_proj_b = (const float*)d_in[6];
    const float* A_log     = (const float*)d_in[7];
    const float* Dw        = (const float*)d_in[8];
    const float* out_proj_w= (const float*)d_in[9];
    const float* U_w       = (const float*)d_in[10];
    const float* V_w       = (const float*)d_in[11];
    const float* ln_g      = (const float*)d_in[12];
    const float* ln_b      = (const float*)d_in[13];
    float* out = (float*)d_out;

    __half *xzh_p, *xah_p, *xdh_p, *dth_p, *ah_p, *bh_p, *wh_p, *wxp_p, *wdt_p;
    cudaGetSymbolAddress((void**)&xzh_p, g_xzh);
    cudaGetSymbolAddress((void**)&xah_p, g_xah);
    cudaGetSymbolAddress((void**)&xdh_p, g_xdh);
    cudaGetSymbolAddress((void**)&dth_p, g_dth);
    cudaGetSymbolAddress((void**)&ah_p, g_ah);
    cudaGetSymbolAddress((void**)&bh_p, g_bh);
    cudaGetSymbolAddress((void**)&wh_p, g_wh);
    cudaGetSymbolAddress((void**)&wxp_p, g_wxp);
    cudaGetSymbolAddress((void**)&wdt_p, g_wdt);

    const int IPW4 = 2*DIN*CEMB/4;
    const int OPW4 = CEMB*DIN/4;

    wcvt_k<<<(IPW4 + 255)/256, 256>>>(in_proj_w, IPW4, 0);
    wcvt_k<<<(IPW4 + 255)/256, 256>>>(in_proj_w + (size_t)2*DIN*CEMB, IPW4, IPW4);
    wcvt_k<<<(OPW4 + 255)/256, 256>>>(out_proj_w, OPW4, 2*IPW4);
    wcvtx_k<<<(64*DIN/4 + 255)/256, 256>>>(x_proj_w, 0);
    wcvtx_k<<<(64*DIN/4 + 255)/256, 256>>>(x_proj_w + (size_t)XD*DIN, 1);
    wcvtd_k<<<(DIN*64 + 255)/256, 256>>>(dt_proj_w, 0);
    wcvtd_k<<<(DIN*64 + 255)/256, 256>>>(dt_proj_w + (size_t)DIN*DTR, 1);
    transpose_k<<<dim3(LLEN/32, CEMB/32, BB), dim3(32, 8)>>>(x);
    prepA_k<<<2, DIN>>>(A_log);
    uf_k<<<1, DIN>>>(U_w, out_proj_w + (size_t)CEMB*DIN);

    for (int mix = 0; mix < 2; mix++) {
        const __half* Ain = (mix == 0) ? ah_p : bh_p;

        gemm_mma<<<dim3((2*DIN)/64, MROWS/128), 256>>>(
            Ain, wh_p + (size_t)mix*IPW4*4, xzh_p, nullptr, MROWS, 2*DIN, CEMB, 1);
        conv_k<<<((MROWS/8)*(DIN/4) + 255)/256, 256>>>(conv_w + mix*DIN*4, conv_b + mix*DIN);
        gemm_mma<<<dim3(1, MROWS/128), 256>>>(
            xah_p, wxp_p + (size_t)mix*64*DIN, xdh_p, nullptr, MROWS, 64, DIN, 1);
        gemm_mma<<<dim3(DIN/64, MROWS/128), 256>>>(
            xdh_p, wdt_p + (size_t)mix*DIN*64, dth_p, dt_proj_b + mix*DIN, MROWS, DIN, 64, 2);
        scan1_k<<<dim3(NC, BB), DIN>>>(mix);
        scan2_k<<<(BB*DIN + 255)/256, 256>>>(mix);
        scan3_k<<<dim3(NC, BB), DIN>>>(Dw + mix*DIN, mix);
        if (mix == 0) {
            gemm_mma<<<dim3(CEMB/64, MROWS/128), 256>>>(
                ah_p, wh_p + (size_t)2*IPW4*4, bh_p, nullptr, MROWS, CEMB, DIN, 1);
        }
    }

    final_k<<<dim3(LLEN/32, BB), 256>>>(V_w, ln_g, ln_b, out);
}